// round 2
// baseline (speedup 1.0000x reference)
#include <cuda_runtime.h>

#define EDIM 1024
#define NH 16
#define HD 64
#define NB 2
#define SQL 1024
#define SKVL 4096
#define MQ (NB*SQL)
#define MKV (NB*SKVL)

// Scratch (allocation-free rule: __device__ globals)
__device__ float g_Q[NB*NH*SQL*HD];    // [b][h][sq][d]
__device__ float g_K[NB*NH*SKVL*HD];   // [b][h][skv][d]
__device__ float g_V[NB*NH*SKVL*HD];
__device__ float g_AO[(size_t)MQ*EDIM];        // attention out [b][sq][e]
__device__ float g_X[(size_t)MQ*EDIM];         // pre-LN residual sum

// ---------------------------------------------------------------------------
// SGEMM C = A @ W^T (+bias, + optional residual / scatter-to-BHSD epilogue)
// Tiles 128x128x8, 256 threads, 8x8 per thread.
// mode 0: scatter to [b][h][s][d] (Sper = seq length); mode 1: plain + residual
// ---------------------------------------------------------------------------
__global__ __launch_bounds__(256) void gemm_nt(
    const float* __restrict__ A, const float* __restrict__ W,
    const float* __restrict__ bias, const float* __restrict__ resid,
    float* __restrict__ Cout, int Sper, int mode)
{
    __shared__ float As[8][128];
    __shared__ float Ws[8][128];
    const int tid = threadIdx.x;
    const int m0 = blockIdx.y * 128;
    const int n0 = blockIdx.x * 128;
    const int lr = tid >> 1;           // 0..127
    const int lk = (tid & 1) << 2;     // 0 or 4
    const float* Ap = A + (size_t)(m0 + lr) * EDIM + lk;
    const float* Wp = W + (size_t)(n0 + lr) * EDIM + lk;

    float acc[8][8];
#pragma unroll
    for (int i = 0; i < 8; i++)
#pragma unroll
        for (int j = 0; j < 8; j++) acc[i][j] = 0.f;

    const int ra = (tid >> 4) << 2;    // 0..60
    const int ca = (tid & 15) << 2;    // 0..60

    float4 av = *(const float4*)Ap;
    float4 wv = *(const float4*)Wp;
    for (int k0 = 0; k0 < EDIM; k0 += 8) {
        __syncthreads();
        As[lk + 0][lr] = av.x; As[lk + 1][lr] = av.y;
        As[lk + 2][lr] = av.z; As[lk + 3][lr] = av.w;
        Ws[lk + 0][lr] = wv.x; Ws[lk + 1][lr] = wv.y;
        Ws[lk + 2][lr] = wv.z; Ws[lk + 3][lr] = wv.w;
        __syncthreads();
        if (k0 + 8 < EDIM) {
            av = *(const float4*)(Ap + k0 + 8);
            wv = *(const float4*)(Wp + k0 + 8);
        }
#pragma unroll
        for (int k = 0; k < 8; k++) {
            float a[8], b[8];
            *(float4*)&a[0] = *(float4*)&As[k][ra];
            *(float4*)&a[4] = *(float4*)&As[k][ra + 64];
            *(float4*)&b[0] = *(float4*)&Ws[k][ca];
            *(float4*)&b[4] = *(float4*)&Ws[k][ca + 64];
#pragma unroll
            for (int i = 0; i < 8; i++)
#pragma unroll
                for (int j = 0; j < 8; j++) acc[i][j] += a[i] * b[j];
        }
    }

#pragma unroll
    for (int i = 0; i < 8; i++) {
        int m = m0 + ra + ((i < 4) ? i : (60 + i));
#pragma unroll
        for (int jh = 0; jh < 2; jh++) {
            int n = n0 + ca + jh * 64;
            float4 bb = *(const float4*)(bias + n);
            float4 r;
            r.x = acc[i][jh * 4 + 0] + bb.x;
            r.y = acc[i][jh * 4 + 1] + bb.y;
            r.z = acc[i][jh * 4 + 2] + bb.z;
            r.w = acc[i][jh * 4 + 3] + bb.w;
            if (mode == 0) {
                int bi = m / Sper, si = m - bi * Sper;
                int h = n >> 6, d = n & 63;
                *(float4*)(Cout + ((size_t)((bi * NH + h) * Sper + si)) * HD + d) = r;
            } else {
                size_t off = (size_t)m * EDIM + n;
                float4 q4 = *(const float4*)(resid + off);
                r.x += q4.x; r.y += q4.y; r.z += q4.z; r.w += q4.w;
                *(float4*)(Cout + off) = r;
            }
        }
    }
}

// ---------------------------------------------------------------------------
// Flash-style attention: one CTA per (q-tile of 64, head, batch).
// 256 threads, 4x4 per thread; online softmax; P staged via smem.
// smem arrays use row stride 68 floats (conflict-free + float4 aligned).
// ---------------------------------------------------------------------------
#define AST 68
__global__ __launch_bounds__(256) void attn_kernel(
    const float* __restrict__ Qg, const float* __restrict__ Kg,
    const float* __restrict__ Vg, const int* __restrict__ maskg,
    float* __restrict__ AO)
{
    extern __shared__ float sm[];
    float* Qs  = sm;                 // [64][AST]  Q^T: Qs[d][i]
    float* KPs = sm + 64 * AST;      // K^T [d][j], then P [i][j]
    float* Vs  = sm + 2 * 64 * AST;  // [j][d]
    __shared__ int msks[64];

    const int tid = threadIdx.x;
    const int tx = tid & 15, ty = tid >> 4;
    const int q0 = blockIdx.x * 64;
    const int h = blockIdx.y, b = blockIdx.z;
    const float* Qb = Qg + ((size_t)((b * NH + h) * SQL + q0)) * HD;
    const float* Kb = Kg + (size_t)(b * NH + h) * SKVL * HD;
    const float* Vb = Vg + (size_t)(b * NH + h) * SKVL * HD;
    const int* mb = maskg + b * SKVL;

    // Load Q tile transposed, pre-scaled by 1/sqrt(D)
    for (int v = tid; v < 1024; v += 256) {
        int i = v >> 4, dq = (v & 15) << 2;
        float4 q4 = *(const float4*)(Qb + i * HD + dq);
        Qs[(dq + 0) * AST + i] = q4.x * 0.125f;
        Qs[(dq + 1) * AST + i] = q4.y * 0.125f;
        Qs[(dq + 2) * AST + i] = q4.z * 0.125f;
        Qs[(dq + 3) * AST + i] = q4.w * 0.125f;
    }

    float m_i[4], l_i[4], o[4][4];
#pragma unroll
    for (int i = 0; i < 4; i++) {
        m_i[i] = -1e30f; l_i[i] = 0.f;
#pragma unroll
        for (int d = 0; d < 4; d++) o[i][d] = 0.f;
    }

    for (int kv0 = 0; kv0 < SKVL; kv0 += 64) {
        __syncthreads();   // previous P/V consumption done
        for (int v = tid; v < 1024; v += 256) {
            int j = v >> 4, dq = (v & 15) << 2;
            float4 k4 = *(const float4*)(Kb + (size_t)(kv0 + j) * HD + dq);
            KPs[(dq + 0) * AST + j] = k4.x;
            KPs[(dq + 1) * AST + j] = k4.y;
            KPs[(dq + 2) * AST + j] = k4.z;
            KPs[(dq + 3) * AST + j] = k4.w;
            *(float4*)&Vs[j * AST + dq] =
                *(const float4*)(Vb + (size_t)(kv0 + j) * HD + dq);
        }
        if (tid < 64) msks[tid] = mb[kv0 + tid];
        __syncthreads();

        float s[4][4];
#pragma unroll
        for (int i = 0; i < 4; i++)
#pragma unroll
            for (int j = 0; j < 4; j++) s[i][j] = 0.f;
#pragma unroll 8
        for (int d = 0; d < 64; d++) {
            float4 qa = *(float4*)&Qs[d * AST + ty * 4];
            float4 kb4 = *(float4*)&KPs[d * AST + tx * 4];
            float a[4] = {qa.x, qa.y, qa.z, qa.w};
            float bb[4] = {kb4.x, kb4.y, kb4.z, kb4.w};
#pragma unroll
            for (int i = 0; i < 4; i++)
#pragma unroll
                for (int j = 0; j < 4; j++) s[i][j] += a[i] * bb[j];
        }
#pragma unroll
        for (int j = 0; j < 4; j++) {
            if (msks[tx * 4 + j] == 0) {
#pragma unroll
                for (int i = 0; i < 4; i++) s[i][j] = -1e30f;
            }
        }
        // online softmax (row stats replicated across the 16-lane row group)
#pragma unroll
        for (int i = 0; i < 4; i++) {
            float mx = fmaxf(fmaxf(s[i][0], s[i][1]), fmaxf(s[i][2], s[i][3]));
#pragma unroll
            for (int off = 8; off; off >>= 1)
                mx = fmaxf(mx, __shfl_xor_sync(0xffffffffu, mx, off));
            float mn = fmaxf(m_i[i], mx);
            float al = __expf(m_i[i] - mn);
            m_i[i] = mn;
            float rs = 0.f;
#pragma unroll
            for (int j = 0; j < 4; j++) { s[i][j] = __expf(s[i][j] - mn); rs += s[i][j]; }
#pragma unroll
            for (int off = 8; off; off >>= 1)
                rs += __shfl_xor_sync(0xffffffffu, rs, off);
            l_i[i] = l_i[i] * al + rs;
#pragma unroll
            for (int d = 0; d < 4; d++) o[i][d] *= al;
        }
        __syncthreads();   // K reads done; reuse KPs for P
#pragma unroll
        for (int i = 0; i < 4; i++)
            *(float4*)&KPs[(ty * 4 + i) * AST + tx * 4] =
                make_float4(s[i][0], s[i][1], s[i][2], s[i][3]);
        __syncthreads();
#pragma unroll 8
        for (int j = 0; j < 64; j++) {
            float4 vv = *(float4*)&Vs[j * AST + tx * 4];
#pragma unroll
            for (int i = 0; i < 4; i++) {
                float p = KPs[(ty * 4 + i) * AST + j];
                o[i][0] += p * vv.x; o[i][1] += p * vv.y;
                o[i][2] += p * vv.z; o[i][3] += p * vv.w;
            }
        }
    }

#pragma unroll
    for (int i = 0; i < 4; i++) {
        float inv = 1.f / l_i[i];
        float4 r = make_float4(o[i][0] * inv, o[i][1] * inv,
                               o[i][2] * inv, o[i][3] * inv);
        size_t off = (size_t)(b * SQL + q0 + ty * 4 + i) * EDIM + h * HD + tx * 4;
        *(float4*)(AO + off) = r;
    }
}

// ---------------------------------------------------------------------------
// Row LayerNorm: one CTA per row of 1024, 256 threads x float4
// ---------------------------------------------------------------------------
__global__ __launch_bounds__(256) void lnorm(
    const float* __restrict__ X, const float* __restrict__ ga,
    const float* __restrict__ be, float* __restrict__ out)
{
    __shared__ float rs[8], rs2[8];
    const int row = blockIdx.x, tid = threadIdx.x;
    const float* x = X + (size_t)row * EDIM;
    float4 v = *(const float4*)(x + tid * 4);
    float s = v.x + v.y + v.z + v.w;
    float s2 = v.x * v.x + v.y * v.y + v.z * v.z + v.w * v.w;
#pragma unroll
    for (int off = 16; off; off >>= 1) {
        s += __shfl_xor_sync(0xffffffffu, s, off);
        s2 += __shfl_xor_sync(0xffffffffu, s2, off);
    }
    if ((tid & 31) == 0) { rs[tid >> 5] = s; rs2[tid >> 5] = s2; }
    __syncthreads();
    if (tid < 32) {
        s = (tid < 8) ? rs[tid] : 0.f;
        s2 = (tid < 8) ? rs2[tid] : 0.f;
#pragma unroll
        for (int off = 4; off; off >>= 1) {
            s += __shfl_xor_sync(0xffffffffu, s, off);
            s2 += __shfl_xor_sync(0xffffffffu, s2, off);
        }
        if (tid == 0) { rs[0] = s; rs2[0] = s2; }
    }
    __syncthreads();
    float mu = rs[0] * (1.f / EDIM);
    float var = rs2[0] * (1.f / EDIM) - mu * mu;
    float r = rsqrtf(var + 1e-5f);
    float4 g4 = *(const float4*)(ga + tid * 4);
    float4 b4 = *(const float4*)(be + tid * 4);
    float4 o4;
    o4.x = (v.x - mu) * r * g4.x + b4.x;
    o4.y = (v.y - mu) * r * g4.y + b4.y;
    o4.z = (v.z - mu) * r * g4.z + b4.z;
    o4.w = (v.w - mu) * r * g4.w + b4.w;
    *(float4*)(out + (size_t)row * EDIM + tid * 4) = o4;
}

// ---------------------------------------------------------------------------
extern "C" void kernel_launch(void* const* d_in, const int* in_sizes, int n_in,
                              void* d_out, int out_size)
{
    const float* query = (const float*)d_in[0];
    const float* kv    = (const float*)d_in[1];
    const int*   mask  = (const int*)d_in[2];
    const float* Wq = (const float*)d_in[3];
    const float* bq = (const float*)d_in[4];
    const float* Wk = (const float*)d_in[5];
    const float* bk = (const float*)d_in[6];
    const float* Wv = (const float*)d_in[7];
    const float* bv = (const float*)d_in[8];
    const float* Wo = (const float*)d_in[9];
    const float* bo = (const float*)d_in[10];
    const float* lng = (const float*)d_in[11];
    const float* lnb = (const float*)d_in[12];
    float* out = (float*)d_out;

    float *Qp, *Kp, *Vp, *AOp, *Xp;
    cudaGetSymbolAddress((void**)&Qp, g_Q);
    cudaGetSymbolAddress((void**)&Kp, g_K);
    cudaGetSymbolAddress((void**)&Vp, g_V);
    cudaGetSymbolAddress((void**)&AOp, g_AO);
    cudaGetSymbolAddress((void**)&Xp, g_X);

    static int smem_set = 0;
    if (!smem_set) {
        cudaFuncSetAttribute(attn_kernel,
                             cudaFuncAttributeMaxDynamicSharedMemorySize,
                             3 * 64 * AST * 4);
        smem_set = 1;
    }

    // Q/K/V projections (scatter into [b][h][s][d])
    gemm_nt<<<dim3(EDIM / 128, MQ / 128), 256>>>(query, Wq, bq, nullptr, Qp, SQL, 0);
    gemm_nt<<<dim3(EDIM / 128, MKV / 128), 256>>>(kv, Wk, bk, nullptr, Kp, SKVL, 0);
    gemm_nt<<<dim3(EDIM / 128, MKV / 128), 256>>>(kv, Wv, bv, nullptr, Vp, SKVL, 0);

    // attention
    attn_kernel<<<dim3(SQL / 64, NH, NB), 256, 3 * 64 * AST * 4>>>(Qp, Kp, Vp, mask, AOp);

    // O projection + residual
    gemm_nt<<<dim3(EDIM / 128, MQ / 128), 256>>>(AOp, Wo, bo, query, Xp, SQL, 1);

    // layernorm
    lnorm<<<MQ, 256>>>(Xp, lng, lnb, out);
}

// round 8
// speedup vs baseline: 1.3324x; 1.3324x over previous
#include <cuda_runtime.h>
#include <cuda_bf16.h>
#include <cstdint>

#define EDIM 1024
#define NH 16
#define HD 64
#define NB 2
#define SQL 1024
#define SKVL 4096
#define MQ (NB*SQL)
#define MKV (NB*SKVL)

// ---------------- scratch (__device__ globals; no allocs allowed) ----------
__device__ __align__(256) float g_Q[NB*NH*SQL*HD];    // [b][h][sq][d]
__device__ __align__(256) float g_K[NB*NH*SKVL*HD];   // [b][h][skv][d]
__device__ __align__(256) float g_V[NB*NH*SKVL*HD];
__device__ __align__(256) float g_AO[(size_t)MQ*EDIM];
__device__ __align__(256) float g_X[(size_t)MQ*EDIM];

// bf16 hi/lo split copies for tensor-core GEMMs
__device__ __align__(256) __nv_bfloat16 g_qh[(size_t)MQ*EDIM],  g_ql[(size_t)MQ*EDIM];
__device__ __align__(256) __nv_bfloat16 g_kvh[(size_t)MKV*EDIM], g_kvl[(size_t)MKV*EDIM];
__device__ __align__(256) __nv_bfloat16 g_aoh[(size_t)MQ*EDIM], g_aol[(size_t)MQ*EDIM];
__device__ __align__(256) __nv_bfloat16 g_wqh[EDIM*EDIM], g_wql[EDIM*EDIM];
__device__ __align__(256) __nv_bfloat16 g_wkh[EDIM*EDIM], g_wkl[EDIM*EDIM];
__device__ __align__(256) __nv_bfloat16 g_wvh[EDIM*EDIM], g_wvl[EDIM*EDIM];
__device__ __align__(256) __nv_bfloat16 g_woh[EDIM*EDIM], g_wol[EDIM*EDIM];

// ---------------- baseline-ISA PTX helpers (sm_80+ features only) ----------
__device__ __forceinline__ uint32_t smem_to_u32(const void* p) {
    uint32_t a;
    asm("{ .reg .u64 t; cvta.to.shared.u64 t, %1; cvt.u32.u64 %0, t; }"
        : "=r"(a) : "l"(p));
    return a;
}
#define CP_ASYNC16(dst, src) \
    asm volatile("cp.async.cg.shared.global [%0], [%1], 16;" :: "r"(dst), "l"(src) : "memory")
#define CP_COMMIT() asm volatile("cp.async.commit_group;" ::: "memory")
#define CP_WAIT1()  asm volatile("cp.async.wait_group 1;" ::: "memory")
#define CP_WAIT0()  asm volatile("cp.async.wait_group 0;" ::: "memory")

__device__ __forceinline__ void ldsm_x4(uint32_t& r0, uint32_t& r1,
                                        uint32_t& r2, uint32_t& r3, uint32_t addr) {
    asm volatile("ldmatrix.sync.aligned.m8n8.x4.shared.b16 {%0,%1,%2,%3}, [%4];"
                 : "=r"(r0), "=r"(r1), "=r"(r2), "=r"(r3) : "r"(addr));
}
__device__ __forceinline__ void mma16816(float* c, const uint32_t* a,
                                         uint32_t b0, uint32_t b1) {
    asm volatile(
        "mma.sync.aligned.m16n8k16.row.col.f32.bf16.bf16.f32 "
        "{%0,%1,%2,%3}, {%4,%5,%6,%7}, {%8,%9}, {%0,%1,%2,%3};"
        : "+f"(c[0]), "+f"(c[1]), "+f"(c[2]), "+f"(c[3])
        : "r"(a[0]), "r"(a[1]), "r"(a[2]), "r"(a[3]), "r"(b0), "r"(b1));
}

// ---------------- fp32 -> bf16 hi/lo split ---------------------------------
__global__ __launch_bounds__(256) void cvt_split(
    const float* __restrict__ x, __nv_bfloat16* __restrict__ h,
    __nv_bfloat16* __restrict__ l, int n4)
{
    int i = blockIdx.x * 256 + threadIdx.x;
    if (i >= n4) return;
    float4 v = ((const float4*)x)[i];
    __nv_bfloat16 h0 = __float2bfloat16(v.x), h1 = __float2bfloat16(v.y);
    __nv_bfloat16 h2 = __float2bfloat16(v.z), h3 = __float2bfloat16(v.w);
    __nv_bfloat16 l0 = __float2bfloat16(v.x - __bfloat162float(h0));
    __nv_bfloat16 l1 = __float2bfloat16(v.y - __bfloat162float(h1));
    __nv_bfloat16 l2 = __float2bfloat16(v.z - __bfloat162float(h2));
    __nv_bfloat16 l3 = __float2bfloat16(v.w - __bfloat162float(h3));
    __nv_bfloat162* hp = (__nv_bfloat162*)h;
    __nv_bfloat162* lp = (__nv_bfloat162*)l;
    hp[2*i] = __nv_bfloat162(h0, h1); hp[2*i + 1] = __nv_bfloat162(h2, h3);
    lp[2*i] = __nv_bfloat162(l0, l1); lp[2*i + 1] = __nv_bfloat162(l2, l3);
}

// ---------------- mma.sync GEMM: C[M,N] = A[M,K] @ W[N,K]^T ----------------
// bf16x3 split: C += Ah*Bh + Ah*Bl + Al*Bh.
// Tile 128x128x32, 256 threads = 8 warps (warp tile 64x32), cp.async double
// buffer, padded smem stride 80B (conflict-free ldmatrix).
// mode 0: +bias, scatter to [b][h][s][d]. mode 1: +bias +residual -> [m][n].
#define BM 128
#define BN 128
#define BK 32
#define SROW 80                    // bytes per smem row (32 bf16 + 8 pad)
#define AHOFF 0
#define ALOFF 10240
#define BHOFF 20480
#define BLOFF 30720
#define STAGE_BYTES 40960
#define GEMM_SMEM (2*STAGE_BYTES)
#define KSTAGES (EDIM/BK)          // 32

__device__ __forceinline__ void load_stage(
    uint32_t sb, int buf, int k0,
    const __nv_bfloat16* Ah, const __nv_bfloat16* Al,
    const __nv_bfloat16* Bh, const __nv_bfloat16* Bl,
    int m0, int n0, int tid)
{
    uint32_t base = sb + buf * STAGE_BYTES;
#pragma unroll
    for (int r = 0; r < 2; r++) {
        int ch = tid + r * 256;          // 512 chunks: 128 rows x 4 x 16B
        int row = ch >> 2, c = ch & 3;
        uint32_t off = (uint32_t)(row * SROW + c * 16);
        const char* gAh = (const char*)(Ah + (size_t)(m0 + row) * EDIM + k0) + c * 16;
        const char* gAl = (const char*)(Al + (size_t)(m0 + row) * EDIM + k0) + c * 16;
        const char* gBh = (const char*)(Bh + (size_t)(n0 + row) * EDIM + k0) + c * 16;
        const char* gBl = (const char*)(Bl + (size_t)(n0 + row) * EDIM + k0) + c * 16;
        CP_ASYNC16(base + AHOFF + off, gAh);
        CP_ASYNC16(base + ALOFF + off, gAl);
        CP_ASYNC16(base + BHOFF + off, gBh);
        CP_ASYNC16(base + BLOFF + off, gBl);
    }
}

__global__ __launch_bounds__(256, 1) void gemm_mma(
    const __nv_bfloat16* __restrict__ Ah, const __nv_bfloat16* __restrict__ Al,
    const __nv_bfloat16* __restrict__ Bh, const __nv_bfloat16* __restrict__ Bl,
    const float* __restrict__ bias, const float* __restrict__ resid,
    float* __restrict__ Cout, int Sper, int mode)
{
    extern __shared__ char smem[];
    uint32_t sb = smem_to_u32(smem);
    const int tid = threadIdx.x, lane = tid & 31, wid = tid >> 5;
    const int m0 = blockIdx.y * BM, n0 = blockIdx.x * BN;
    const int wm = (wid & 1) * 64;     // warp M offset in tile
    const int wn = (wid >> 1) * 32;    // warp N offset in tile

    float acc[4][4][4];
#pragma unroll
    for (int i = 0; i < 4; i++)
#pragma unroll
        for (int j = 0; j < 4; j++)
#pragma unroll
            for (int t = 0; t < 4; t++) acc[i][j][t] = 0.f;

    load_stage(sb, 0, 0, Ah, Al, Bh, Bl, m0, n0, tid);
    CP_COMMIT();

    const int rl = lane & 15;
    for (int kt = 0; kt < KSTAGES; kt++) {
        if (kt + 1 < KSTAGES) {
            load_stage(sb, (kt + 1) & 1, (kt + 1) * BK, Ah, Al, Bh, Bl, m0, n0, tid);
            CP_COMMIT();
            CP_WAIT1();
        } else {
            CP_WAIT0();
        }
        __syncthreads();
        uint32_t base = sb + (kt & 1) * STAGE_BYTES;
#pragma unroll
        for (int kk = 0; kk < 2; kk++) {
            uint32_t rcol = (uint32_t)((kk * 16 + ((lane >> 4) << 3)) << 1);
            uint32_t ah[4][4], al[4][4];
#pragma unroll
            for (int im = 0; im < 4; im++) {
                uint32_t ad = base + (uint32_t)((wm + im * 16 + rl) * SROW) + rcol;
                ldsm_x4(ah[im][0], ah[im][1], ah[im][2], ah[im][3], ad + AHOFF);
                ldsm_x4(al[im][0], al[im][1], al[im][2], al[im][3], ad + ALOFF);
            }
            uint32_t bh[4][2], bl[4][2];
#pragma unroll
            for (int pr = 0; pr < 2; pr++) {
                uint32_t bd = base + (uint32_t)((wn + pr * 16 + rl) * SROW) + rcol;
                uint32_t t0, t1, t2, t3;
                ldsm_x4(t0, t1, t2, t3, bd + BHOFF);
                bh[pr*2][0] = t0; bh[pr*2+1][0] = t1;
                bh[pr*2][1] = t2; bh[pr*2+1][1] = t3;
                ldsm_x4(t0, t1, t2, t3, bd + BLOFF);
                bl[pr*2][0] = t0; bl[pr*2+1][0] = t1;
                bl[pr*2][1] = t2; bl[pr*2+1][1] = t3;
            }
#pragma unroll
            for (int im = 0; im < 4; im++)
#pragma unroll
                for (int in = 0; in < 4; in++) {
                    mma16816(acc[im][in], ah[im], bh[in][0], bh[in][1]);
                    mma16816(acc[im][in], ah[im], bl[in][0], bl[in][1]);
                    mma16816(acc[im][in], al[im], bh[in][0], bh[in][1]);
                }
        }
        __syncthreads();
    }

    // epilogue: c fragment lane mapping — rows (lane>>2) & +8, cols (lane&3)*2..+1
    const int mr = m0 + wm + (lane >> 2);
    const int nc = n0 + wn + (lane & 3) * 2;
#pragma unroll
    for (int im = 0; im < 4; im++) {
#pragma unroll
        for (int half = 0; half < 2; half++) {
            const int m = mr + im * 16 + half * 8;
            const int bi = m / Sper, si = m - bi * Sper;
#pragma unroll
            for (int in = 0; in < 4; in++) {
                const int n = nc + in * 8;
                float c0 = acc[im][in][half * 2 + 0] + bias[n];
                float c1 = acc[im][in][half * 2 + 1] + bias[n + 1];
                if (mode == 0) {
                    const int h = n >> 6, d = n & 63;
                    float* dst = Cout + ((size_t)((bi * NH + h) * Sper + si)) * HD + d;
                    *(float2*)dst = make_float2(c0, c1);
                } else {
                    const size_t off = (size_t)m * EDIM + n;
                    float2 q2 = *(const float2*)(resid + off);
                    *(float2*)(Cout + off) = make_float2(c0 + q2.x, c1 + q2.y);
                }
            }
        }
    }
}

// ---------------- flash attention (fp32, unchanged) ------------------------
#define AST 68
__global__ __launch_bounds__(256) void attn_kernel(
    const float* __restrict__ Qg, const float* __restrict__ Kg,
    const float* __restrict__ Vg, const int* __restrict__ maskg,
    float* __restrict__ AO)
{
    extern __shared__ float sm[];
    float* Qs  = sm;
    float* KPs = sm + 64 * AST;
    float* Vs  = sm + 2 * 64 * AST;
    __shared__ int msks[64];

    const int tid = threadIdx.x;
    const int tx = tid & 15, ty = tid >> 4;
    const int q0 = blockIdx.x * 64;
    const int h = blockIdx.y, b = blockIdx.z;
    const float* Qb = Qg + ((size_t)((b * NH + h) * SQL + q0)) * HD;
    const float* Kb = Kg + (size_t)(b * NH + h) * SKVL * HD;
    const float* Vb = Vg + (size_t)(b * NH + h) * SKVL * HD;
    const int* mb = maskg + b * SKVL;

    for (int v = tid; v < 1024; v += 256) {
        int i = v >> 4, dq = (v & 15) << 2;
        float4 q4 = *(const float4*)(Qb + i * HD + dq);
        Qs[(dq + 0) * AST + i] = q4.x * 0.125f;
        Qs[(dq + 1) * AST + i] = q4.y * 0.125f;
        Qs[(dq + 2) * AST + i] = q4.z * 0.125f;
        Qs[(dq + 3) * AST + i] = q4.w * 0.125f;
    }

    float m_i[4], l_i[4], o[4][4];
#pragma unroll
    for (int i = 0; i < 4; i++) {
        m_i[i] = -1e30f; l_i[i] = 0.f;
#pragma unroll
        for (int d = 0; d < 4; d++) o[i][d] = 0.f;
    }

    for (int kv0 = 0; kv0 < SKVL; kv0 += 64) {
        __syncthreads();
        for (int v = tid; v < 1024; v += 256) {
            int j = v >> 4, dq = (v & 15) << 2;
            float4 k4 = *(const float4*)(Kb + (size_t)(kv0 + j) * HD + dq);
            KPs[(dq + 0) * AST + j] = k4.x;
            KPs[(dq + 1) * AST + j] = k4.y;
            KPs[(dq + 2) * AST + j] = k4.z;
            KPs[(dq + 3) * AST + j] = k4.w;
            *(float4*)&Vs[j * AST + dq] =
                *(const float4*)(Vb + (size_t)(kv0 + j) * HD + dq);
        }
        if (tid < 64) msks[tid] = mb[kv0 + tid];
        __syncthreads();

        float s[4][4];
#pragma unroll
        for (int i = 0; i < 4; i++)
#pragma unroll
            for (int j = 0; j < 4; j++) s[i][j] = 0.f;
#pragma unroll 8
        for (int d = 0; d < 64; d++) {
            float4 qa = *(float4*)&Qs[d * AST + ty * 4];
            float4 kb4 = *(float4*)&KPs[d * AST + tx * 4];
            float a[4] = {qa.x, qa.y, qa.z, qa.w};
            float bb[4] = {kb4.x, kb4.y, kb4.z, kb4.w};
#pragma unroll
            for (int i = 0; i < 4; i++)
#pragma unroll
                for (int j = 0; j < 4; j++) s[i][j] += a[i] * bb[j];
        }
#pragma unroll
        for (int j = 0; j < 4; j++) {
            if (msks[tx * 4 + j] == 0) {
#pragma unroll
                for (int i = 0; i < 4; i++) s[i][j] = -1e30f;
            }
        }
#pragma unroll
        for (int i = 0; i < 4; i++) {
            float mx = fmaxf(fmaxf(s[i][0], s[i][1]), fmaxf(s[i][2], s[i][3]));
#pragma unroll
            for (int off = 8; off; off >>= 1)
                mx = fmaxf(mx, __shfl_xor_sync(0xffffffffu, mx, off));
            float mn = fmaxf(m_i[i], mx);
            float al = __expf(m_i[i] - mn);
            m_i[i] = mn;
            float rs = 0.f;
#pragma unroll
            for (int j = 0; j < 4; j++) { s[i][j] = __expf(s[i][j] - mn); rs += s[i][j]; }
#pragma unroll
            for (int off = 8; off; off >>= 1)
                rs += __shfl_xor_sync(0xffffffffu, rs, off);
            l_i[i] = l_i[i] * al + rs;
#pragma unroll
            for (int d = 0; d < 4; d++) o[i][d] *= al;
        }
        __syncthreads();
#pragma unroll
        for (int i = 0; i < 4; i++)
            *(float4*)&KPs[(ty * 4 + i) * AST + tx * 4] =
                make_float4(s[i][0], s[i][1], s[i][2], s[i][3]);
        __syncthreads();
#pragma unroll 8
        for (int j = 0; j < 64; j++) {
            float4 vv = *(float4*)&Vs[j * AST + tx * 4];
#pragma unroll
            for (int i = 0; i < 4; i++) {
                float p = KPs[(ty * 4 + i) * AST + j];
                o[i][0] += p * vv.x; o[i][1] += p * vv.y;
                o[i][2] += p * vv.z; o[i][3] += p * vv.w;
            }
        }
    }

#pragma unroll
    for (int i = 0; i < 4; i++) {
        float inv = 1.f / l_i[i];
        float4 r = make_float4(o[i][0] * inv, o[i][1] * inv,
                               o[i][2] * inv, o[i][3] * inv);
        size_t off = (size_t)(b * SQL + q0 + ty * 4 + i) * EDIM + h * HD + tx * 4;
        *(float4*)(AO + off) = r;
    }
}

// ---------------- LayerNorm (unchanged) ------------------------------------
__global__ __launch_bounds__(256) void lnorm(
    const float* __restrict__ X, const float* __restrict__ ga,
    const float* __restrict__ be, float* __restrict__ out)
{
    __shared__ float rs[8], rs2[8];
    const int row = blockIdx.x, tid = threadIdx.x;
    const float* x = X + (size_t)row * EDIM;
    float4 v = *(const float4*)(x + tid * 4);
    float s = v.x + v.y + v.z + v.w;
    float s2 = v.x * v.x + v.y * v.y + v.z * v.z + v.w * v.w;
#pragma unroll
    for (int off = 16; off; off >>= 1) {
        s += __shfl_xor_sync(0xffffffffu, s, off);
        s2 += __shfl_xor_sync(0xffffffffu, s2, off);
    }
    if ((tid & 31) == 0) { rs[tid >> 5] = s; rs2[tid >> 5] = s2; }
    __syncthreads();
    if (tid < 32) {
        s = (tid < 8) ? rs[tid] : 0.f;
        s2 = (tid < 8) ? rs2[tid] : 0.f;
#pragma unroll
        for (int off = 4; off; off >>= 1) {
            s += __shfl_xor_sync(0xffffffffu, s, off);
            s2 += __shfl_xor_sync(0xffffffffu, s2, off);
        }
        if (tid == 0) { rs[0] = s; rs2[0] = s2; }
    }
    __syncthreads();
    float mu = rs[0] * (1.f / EDIM);
    float var = rs2[0] * (1.f / EDIM) - mu * mu;
    float r = rsqrtf(var + 1e-5f);
    float4 g4 = *(const float4*)(ga + tid * 4);
    float4 b4 = *(const float4*)(be + tid * 4);
    float4 o4;
    o4.x = (v.x - mu) * r * g4.x + b4.x;
    o4.y = (v.y - mu) * r * g4.y + b4.y;
    o4.z = (v.z - mu) * r * g4.z + b4.z;
    o4.w = (v.w - mu) * r * g4.w + b4.w;
    *(float4*)(out + (size_t)row * EDIM + tid * 4) = o4;
}

// ---------------------------------------------------------------------------
extern "C" void kernel_launch(void* const* d_in, const int* in_sizes, int n_in,
                              void* d_out, int out_size)
{
    const float* query = (const float*)d_in[0];
    const float* kv    = (const float*)d_in[1];
    const int*   mask  = (const int*)d_in[2];
    const float* Wq = (const float*)d_in[3];
    const float* bq = (const float*)d_in[4];
    const float* Wk = (const float*)d_in[5];
    const float* bk = (const float*)d_in[6];
    const float* Wv = (const float*)d_in[7];
    const float* bv = (const float*)d_in[8];
    const float* Wo = (const float*)d_in[9];
    const float* bo = (const float*)d_in[10];
    const float* lng = (const float*)d_in[11];
    const float* lnb = (const float*)d_in[12];
    float* out = (float*)d_out;

    float *Qp, *Kp, *Vp, *AOp, *Xp;
    cudaGetSymbolAddress((void**)&Qp, g_Q);
    cudaGetSymbolAddress((void**)&Kp, g_K);
    cudaGetSymbolAddress((void**)&Vp, g_V);
    cudaGetSymbolAddress((void**)&AOp, g_AO);
    cudaGetSymbolAddress((void**)&Xp, g_X);

    __nv_bfloat16 *qh, *ql, *kvh, *kvl, *aoh, *aol;
    __nv_bfloat16 *wqh, *wql, *wkh, *wkl, *wvh, *wvl, *woh, *wol;
    cudaGetSymbolAddress((void**)&qh, g_qh);   cudaGetSymbolAddress((void**)&ql, g_ql);
    cudaGetSymbolAddress((void**)&kvh, g_kvh); cudaGetSymbolAddress((void**)&kvl, g_kvl);
    cudaGetSymbolAddress((void**)&aoh, g_aoh); cudaGetSymbolAddress((void**)&aol, g_aol);
    cudaGetSymbolAddress((void**)&wqh, g_wqh); cudaGetSymbolAddress((void**)&wql, g_wql);
    cudaGetSymbolAddress((void**)&wkh, g_wkh); cudaGetSymbolAddress((void**)&wkl, g_wkl);
    cudaGetSymbolAddress((void**)&wvh, g_wvh); cudaGetSymbolAddress((void**)&wvl, g_wvl);
    cudaGetSymbolAddress((void**)&woh, g_woh); cudaGetSymbolAddress((void**)&wol, g_wol);

    static int attr_set = 0;
    if (!attr_set) {
        cudaFuncSetAttribute(attn_kernel,
                             cudaFuncAttributeMaxDynamicSharedMemorySize, 3 * 64 * AST * 4);
        cudaFuncSetAttribute(gemm_mma,
                             cudaFuncAttributeMaxDynamicSharedMemorySize, GEMM_SMEM);
        attr_set = 1;
    }

    // bf16 hi/lo conversions
    const int W4 = EDIM * EDIM / 4;
    cvt_split<<<(MQ * EDIM / 4 + 255) / 256, 256>>>(query, qh, ql, MQ * EDIM / 4);
    cvt_split<<<(MKV * EDIM / 4 + 255) / 256, 256>>>(kv, kvh, kvl, MKV * EDIM / 4);
    cvt_split<<<(W4 + 255) / 256, 256>>>(Wq, wqh, wql, W4);
    cvt_split<<<(W4 + 255) / 256, 256>>>(Wk, wkh, wkl, W4);
    cvt_split<<<(W4 + 255) / 256, 256>>>(Wv, wvh, wvl, W4);
    cvt_split<<<(W4 + 255) / 256, 256>>>(Wo, woh, wol, W4);

    // Q/K/V projections on tensor cores (scatter into [b][h][s][d] fp32)
    gemm_mma<<<dim3(EDIM / BN, MQ / BM), 256, GEMM_SMEM>>>(
        qh, ql, wqh, wql, bq, nullptr, Qp, SQL, 0);
    gemm_mma<<<dim3(EDIM / BN, MKV / BM), 256, GEMM_SMEM>>>(
        kvh, kvl, wkh, wkl, bk, nullptr, Kp, SKVL, 0);
    gemm_mma<<<dim3(EDIM / BN, MKV / BM), 256, GEMM_SMEM>>>(
        kvh, kvl, wvh, wvl, bv, nullptr, Vp, SKVL, 0);

    // attention (fp32)
    attn_kernel<<<dim3(SQL / 64, NH, NB), 256, 3 * 64 * AST * 4>>>(Qp, Kp, Vp, mask, AOp);

    // O projection + residual on tensor cores
    cvt_split<<<(MQ * EDIM / 4 + 255) / 256, 256>>>(AOp, aoh, aol, MQ * EDIM / 4);
    gemm_mma<<<dim3(EDIM / BN, MQ / BM), 256, GEMM_SMEM>>>(
        aoh, aol, woh, wol, bo, query, Xp, SQL, 1);

    // layernorm
    lnorm<<<MQ, 256>>>(Xp, lng, lnb, out);
}

// round 11
// speedup vs baseline: 3.0059x; 2.2559x over previous
#include <cuda_runtime.h>
#include <cuda_bf16.h>
#include <cstdint>

#define EDIM 1024
#define NH 16
#define HD 64
#define NB 2
#define SQL 1024
#define SKVL 4096
#define MQ (NB*SQL)
#define MKV (NB*SKVL)

// ---------------- scratch (__device__ globals; no allocs allowed) ----------
__device__ __align__(256) __nv_bfloat16 g_Qb[(size_t)NB*NH*SQL*HD];   // [b][h][sq][d]
__device__ __align__(256) __nv_bfloat16 g_Kb[(size_t)NB*NH*SKVL*HD];
__device__ __align__(256) __nv_bfloat16 g_Vb[(size_t)NB*NH*SKVL*HD];
__device__ __align__(256) float g_X[(size_t)MQ*EDIM];

__device__ __align__(256) __nv_bfloat16 g_qh[(size_t)MQ*EDIM],  g_ql[(size_t)MQ*EDIM];
__device__ __align__(256) __nv_bfloat16 g_kvh[(size_t)MKV*EDIM], g_kvl[(size_t)MKV*EDIM];
__device__ __align__(256) __nv_bfloat16 g_aoh[(size_t)MQ*EDIM], g_aol[(size_t)MQ*EDIM];
__device__ __align__(256) __nv_bfloat16 g_wqh[EDIM*EDIM], g_wql[EDIM*EDIM];
__device__ __align__(256) __nv_bfloat16 g_wkh[EDIM*EDIM], g_wkl[EDIM*EDIM];
__device__ __align__(256) __nv_bfloat16 g_wvh[EDIM*EDIM], g_wvl[EDIM*EDIM];
__device__ __align__(256) __nv_bfloat16 g_woh[EDIM*EDIM], g_wol[EDIM*EDIM];

// ---------------- baseline-ISA helpers ------------------------------------
__device__ __forceinline__ uint32_t smem_to_u32(const void* p) {
    uint32_t a;
    asm("{ .reg .u64 t; cvta.to.shared.u64 t, %1; cvt.u32.u64 %0, t; }"
        : "=r"(a) : "l"(p));
    return a;
}
#define CP_ASYNC16(dst, src) \
    asm volatile("cp.async.cg.shared.global [%0], [%1], 16;" :: "r"(dst), "l"(src) : "memory")
#define CP_COMMIT() asm volatile("cp.async.commit_group;" ::: "memory")
#define CP_WAIT1()  asm volatile("cp.async.wait_group 1;" ::: "memory")
#define CP_WAIT0()  asm volatile("cp.async.wait_group 0;" ::: "memory")

__device__ __forceinline__ void ldsm_x4(uint32_t& r0, uint32_t& r1,
                                        uint32_t& r2, uint32_t& r3, uint32_t addr) {
    asm volatile("ldmatrix.sync.aligned.m8n8.x4.shared.b16 {%0,%1,%2,%3}, [%4];"
                 : "=r"(r0), "=r"(r1), "=r"(r2), "=r"(r3) : "r"(addr));
}
__device__ __forceinline__ void ldsm_x4_t(uint32_t& r0, uint32_t& r1,
                                          uint32_t& r2, uint32_t& r3, uint32_t addr) {
    asm volatile("ldmatrix.sync.aligned.m8n8.x4.trans.shared.b16 {%0,%1,%2,%3}, [%4];"
                 : "=r"(r0), "=r"(r1), "=r"(r2), "=r"(r3) : "r"(addr));
}
__device__ __forceinline__ void mma16816(float* c, const uint32_t* a,
                                         uint32_t b0, uint32_t b1) {
    asm volatile(
        "mma.sync.aligned.m16n8k16.row.col.f32.bf16.bf16.f32 "
        "{%0,%1,%2,%3}, {%4,%5,%6,%7}, {%8,%9}, {%0,%1,%2,%3};"
        : "+f"(c[0]), "+f"(c[1]), "+f"(c[2]), "+f"(c[3])
        : "r"(a[0]), "r"(a[1]), "r"(a[2]), "r"(a[3]), "r"(b0), "r"(b1));
}
__device__ __forceinline__ float ex2f(float x) {
    float y; asm("ex2.approx.f32 %0, %1;" : "=f"(y) : "f"(x)); return y;
}
// packs lo into low half, hi into high half
__device__ __forceinline__ uint32_t pack_bf16x2(float lo, float hi) {
    uint32_t r; asm("cvt.rn.bf16x2.f32 %0, %1, %2;" : "=r"(r) : "f"(hi), "f"(lo));
    return r;
}

// ---------------- fp32 -> bf16 hi/lo split ---------------------------------
__global__ __launch_bounds__(256) void cvt_split(
    const float* __restrict__ x, __nv_bfloat16* __restrict__ h,
    __nv_bfloat16* __restrict__ l, int n4)
{
    int i = blockIdx.x * 256 + threadIdx.x;
    if (i >= n4) return;
    float4 v = ((const float4*)x)[i];
    __nv_bfloat16 h0 = __float2bfloat16(v.x), h1 = __float2bfloat16(v.y);
    __nv_bfloat16 h2 = __float2bfloat16(v.z), h3 = __float2bfloat16(v.w);
    __nv_bfloat16 l0 = __float2bfloat16(v.x - __bfloat162float(h0));
    __nv_bfloat16 l1 = __float2bfloat16(v.y - __bfloat162float(h1));
    __nv_bfloat16 l2 = __float2bfloat16(v.z - __bfloat162float(h2));
    __nv_bfloat16 l3 = __float2bfloat16(v.w - __bfloat162float(h3));
    __nv_bfloat162* hp = (__nv_bfloat162*)h;
    __nv_bfloat162* lp = (__nv_bfloat162*)l;
    hp[2*i] = __nv_bfloat162(h0, h1); hp[2*i + 1] = __nv_bfloat162(h2, h3);
    lp[2*i] = __nv_bfloat162(l0, l1); lp[2*i + 1] = __nv_bfloat162(l2, l3);
}

// ---------------- mma.sync GEMM: C[M,N] = A[M,K] @ W[N,K]^T ----------------
// bf16x3 split: C += Ah*Bh + Ah*Bl + Al*Bh (pass-reordered: no acc RAW chains)
// mode 0: +bias, bf16 scatter to [b][h][s][d]. mode 1: +bias+residual fp32.
#define BM 128
#define BN 128
#define BK 32
#define SROW 80
#define AHOFF 0
#define ALOFF 10240
#define BHOFF 20480
#define BLOFF 30720
#define STAGE_BYTES 40960
#define GEMM_SMEM (2*STAGE_BYTES)
#define KSTAGES (EDIM/BK)

__device__ __forceinline__ void load_stage(
    uint32_t sb, int buf, int k0,
    const __nv_bfloat16* Ah, const __nv_bfloat16* Al,
    const __nv_bfloat16* Bh, const __nv_bfloat16* Bl,
    int m0, int n0, int tid)
{
    uint32_t base = sb + buf * STAGE_BYTES;
#pragma unroll
    for (int r = 0; r < 2; r++) {
        int ch = tid + r * 256;
        int row = ch >> 2, c = ch & 3;
        uint32_t off = (uint32_t)(row * SROW + c * 16);
        const char* gAh = (const char*)(Ah + (size_t)(m0 + row) * EDIM + k0) + c * 16;
        const char* gAl = (const char*)(Al + (size_t)(m0 + row) * EDIM + k0) + c * 16;
        const char* gBh = (const char*)(Bh + (size_t)(n0 + row) * EDIM + k0) + c * 16;
        const char* gBl = (const char*)(Bl + (size_t)(n0 + row) * EDIM + k0) + c * 16;
        CP_ASYNC16(base + AHOFF + off, gAh);
        CP_ASYNC16(base + ALOFF + off, gAl);
        CP_ASYNC16(base + BHOFF + off, gBh);
        CP_ASYNC16(base + BLOFF + off, gBl);
    }
}

__global__ __launch_bounds__(256, 1) void gemm_mma(
    const __nv_bfloat16* __restrict__ Ah, const __nv_bfloat16* __restrict__ Al,
    const __nv_bfloat16* __restrict__ Bh, const __nv_bfloat16* __restrict__ Bl,
    const float* __restrict__ bias, const float* __restrict__ resid,
    void* __restrict__ Cout, int Sper, int mode)
{
    extern __shared__ char smem[];
    uint32_t sb = smem_to_u32(smem);
    const int tid = threadIdx.x, lane = tid & 31, wid = tid >> 5;
    const int m0 = blockIdx.y * BM, n0 = blockIdx.x * BN;
    const int wm = (wid & 1) * 64;
    const int wn = (wid >> 1) * 32;

    float acc[4][4][4];
#pragma unroll
    for (int i = 0; i < 4; i++)
#pragma unroll
        for (int j = 0; j < 4; j++)
#pragma unroll
            for (int t = 0; t < 4; t++) acc[i][j][t] = 0.f;

    load_stage(sb, 0, 0, Ah, Al, Bh, Bl, m0, n0, tid);
    CP_COMMIT();

    const int rl = lane & 15;
    for (int kt = 0; kt < KSTAGES; kt++) {
        if (kt + 1 < KSTAGES) {
            load_stage(sb, (kt + 1) & 1, (kt + 1) * BK, Ah, Al, Bh, Bl, m0, n0, tid);
            CP_COMMIT();
            CP_WAIT1();
        } else {
            CP_WAIT0();
        }
        __syncthreads();
        uint32_t base = sb + (kt & 1) * STAGE_BYTES;
#pragma unroll
        for (int kk = 0; kk < 2; kk++) {
            uint32_t rcol = (uint32_t)((kk * 16 + ((lane >> 4) << 3)) << 1);
            uint32_t ah[4][4], al[4][4];
#pragma unroll
            for (int im = 0; im < 4; im++) {
                uint32_t ad = base + (uint32_t)((wm + im * 16 + rl) * SROW) + rcol;
                ldsm_x4(ah[im][0], ah[im][1], ah[im][2], ah[im][3], ad + AHOFF);
                ldsm_x4(al[im][0], al[im][1], al[im][2], al[im][3], ad + ALOFF);
            }
            uint32_t bh[4][2], bl[4][2];
#pragma unroll
            for (int pr = 0; pr < 2; pr++) {
                uint32_t bd = base + (uint32_t)((wn + pr * 16 + rl) * SROW) + rcol;
                uint32_t t0, t1, t2, t3;
                ldsm_x4(t0, t1, t2, t3, bd + BHOFF);
                bh[pr*2][0] = t0; bh[pr*2+1][0] = t1;
                bh[pr*2][1] = t2; bh[pr*2+1][1] = t3;
                ldsm_x4(t0, t1, t2, t3, bd + BLOFF);
                bl[pr*2][0] = t0; bl[pr*2+1][0] = t1;
                bl[pr*2][1] = t2; bl[pr*2+1][1] = t3;
            }
            // three passes -> 16 independent accumulators per pass (no RAW chains)
#pragma unroll
            for (int im = 0; im < 4; im++)
#pragma unroll
                for (int in = 0; in < 4; in++)
                    mma16816(acc[im][in], ah[im], bh[in][0], bh[in][1]);
#pragma unroll
            for (int im = 0; im < 4; im++)
#pragma unroll
                for (int in = 0; in < 4; in++)
                    mma16816(acc[im][in], ah[im], bl[in][0], bl[in][1]);
#pragma unroll
            for (int im = 0; im < 4; im++)
#pragma unroll
                for (int in = 0; in < 4; in++)
                    mma16816(acc[im][in], al[im], bh[in][0], bh[in][1]);
        }
        __syncthreads();
    }

    const int mr = m0 + wm + (lane >> 2);
    const int nc = n0 + wn + (lane & 3) * 2;
#pragma unroll
    for (int im = 0; im < 4; im++) {
#pragma unroll
        for (int half = 0; half < 2; half++) {
            const int m = mr + im * 16 + half * 8;
            const int bi = m / Sper, si = m - bi * Sper;
#pragma unroll
            for (int in = 0; in < 4; in++) {
                const int n = nc + in * 8;
                float c0 = acc[im][in][half * 2 + 0] + bias[n];
                float c1 = acc[im][in][half * 2 + 1] + bias[n + 1];
                if (mode == 0) {
                    const int h = n >> 6, d = n & 63;
                    __nv_bfloat16* dst = (__nv_bfloat16*)Cout +
                        ((size_t)((bi * NH + h) * Sper + si)) * HD + d;
                    *(uint32_t*)dst = pack_bf16x2(c0, c1);
                } else {
                    const size_t off = (size_t)m * EDIM + n;
                    float2 q2 = *(const float2*)(resid + off);
                    *(float2*)((float*)Cout + off) = make_float2(c0 + q2.x, c1 + q2.y);
                }
            }
        }
    }
}

// ---------------- tensor-core flash attention ------------------------------
// CTA: 128 q-rows x (head, batch); 8 warps x 16 rows; KV tiles of 64,
// double-buffered cp.async. S via bf16 MMA, softmax fp32 (ex2.approx, 1/8
// scale folded into CEXP, mask as -1e30 additive bias), P repacked in-register
// to bf16x2 A-frags, PV via trans-ldmatrix V frags. Emits hi/lo-split AO.
#define ASTRH 72
#define ASTRB 144
#define ATILEB (64*ASTRB)
#define AQ_OFF 0
#define AK_OFF (128*ASTRB)
#define AV_OFF (AK_OFF + 2*ATILEB)
#define AB_OFF (AV_OFF + 2*ATILEB)
#define ATT_SMEM (AB_OFF + 2*64*4)
#define NKV (SKVL/64)
#define CEXP 0.18033688f  /* log2(e)/8 */

__device__ __forceinline__ void load_kv_tile(
    uint32_t sb, int buf, int kv0,
    const __nv_bfloat16* Kb, const __nv_bfloat16* Vb, int tid)
{
#pragma unroll
    for (int i = 0; i < 2; i++) {
        int ch = tid + i * 256;                  // 512 chunks each
        int row = ch >> 3, c = ch & 7;
        uint32_t off = (uint32_t)(buf * ATILEB + row * ASTRB + c * 16);
        CP_ASYNC16(sb + AK_OFF + off, (const char*)(Kb + (size_t)(kv0 + row) * HD) + c * 16);
        CP_ASYNC16(sb + AV_OFF + off, (const char*)(Vb + (size_t)(kv0 + row) * HD) + c * 16);
    }
}

__global__ __launch_bounds__(256, 1) void attn_mma(
    const __nv_bfloat16* __restrict__ Qg, const __nv_bfloat16* __restrict__ Kg,
    const __nv_bfloat16* __restrict__ Vg, const int* __restrict__ maskg,
    __nv_bfloat16* __restrict__ AOh, __nv_bfloat16* __restrict__ AOl)
{
    extern __shared__ char smem[];
    uint32_t sb = smem_to_u32(smem);
    float* biasS = (float*)(smem + AB_OFF);
    const int tid = threadIdx.x, lane = tid & 31, wid = tid >> 5;
    const int q0 = blockIdx.x * 128;
    const int h = blockIdx.y, b = blockIdx.z;
    const __nv_bfloat16* Qb = Qg + ((size_t)((b * NH + h) * SQL + q0)) * HD;
    const __nv_bfloat16* Kb = Kg + (size_t)(b * NH + h) * SKVL * HD;
    const __nv_bfloat16* Vb = Vg + (size_t)(b * NH + h) * SKVL * HD;
    const int* mb = maskg + b * SKVL;
    const int wm = wid * 16;

    // Q tile (1024 chunks) + KV tile 0, one cp.async group
#pragma unroll
    for (int i = 0; i < 4; i++) {
        int ch = tid + i * 256;
        int row = ch >> 3, c = ch & 7;
        CP_ASYNC16(sb + AQ_OFF + row * ASTRB + c * 16,
                   (const char*)(Qb + row * HD) + c * 16);
    }
    load_kv_tile(sb, 0, 0, Kb, Vb, tid);
    CP_COMMIT();
    if (tid < 64) biasS[tid] = mb[tid] ? 0.f : -1e30f;

    float m0r = -1e30f, m1r = -1e30f, lr0 = 0.f, lr1 = 0.f;
    float o[8][4];
#pragma unroll
    for (int j = 0; j < 8; j++)
#pragma unroll
        for (int t = 0; t < 4; t++) o[j][t] = 0.f;

    for (int kt = 0; kt < NKV; kt++) {
        const int buf = kt & 1;
        if (kt + 1 < NKV) {
            load_kv_tile(sb, buf ^ 1, (kt + 1) * 64, Kb, Vb, tid);
            if (tid < 64)
                biasS[64 * (buf ^ 1) + tid] = mb[(kt + 1) * 64 + tid] ? 0.f : -1e30f;
            CP_COMMIT();
            CP_WAIT1();
        } else {
            CP_WAIT0();
        }
        __syncthreads();

        // ---- S = Q K^T  (warp: 16 rows x 64 kv) ----
        float s[8][4];
#pragma unroll
        for (int j = 0; j < 8; j++)
#pragma unroll
            for (int t = 0; t < 4; t++) s[j][t] = 0.f;
#pragma unroll
        for (int kk = 0; kk < 4; kk++) {
            uint32_t a[4];
            ldsm_x4(a[0], a[1], a[2], a[3],
                    sb + AQ_OFF + (uint32_t)((wm + (lane & 15)) * ASTRB)
                    + (uint32_t)(kk * 32 + (lane >> 4) * 16));
#pragma unroll
            for (int jp = 0; jp < 4; jp++) {
                uint32_t b0, b1, b2, b3;
                ldsm_x4(b0, b1, b2, b3,
                        sb + AK_OFF + buf * ATILEB
                        + (uint32_t)((jp * 16 + (lane & 7) + ((lane >> 4) & 1) * 8) * ASTRB)
                        + (uint32_t)(kk * 32 + ((lane >> 3) & 1) * 16));
                mma16816(s[jp * 2],     a, b0, b1);
                mma16816(s[jp * 2 + 1], a, b2, b3);
            }
        }

        // ---- mask bias + online softmax ----
        const int qr = (lane & 3) * 2;
        float t0 = -1e30f, t1 = -1e30f;
#pragma unroll
        for (int j = 0; j < 8; j++) {
            float2 bv = *(float2*)&biasS[buf * 64 + j * 8 + qr];
            s[j][0] += bv.x; s[j][1] += bv.y;
            s[j][2] += bv.x; s[j][3] += bv.y;
            t0 = fmaxf(t0, fmaxf(s[j][0], s[j][1]));
            t1 = fmaxf(t1, fmaxf(s[j][2], s[j][3]));
        }
        t0 = fmaxf(t0, __shfl_xor_sync(0xffffffffu, t0, 1));
        t0 = fmaxf(t0, __shfl_xor_sync(0xffffffffu, t0, 2));
        t1 = fmaxf(t1, __shfl_xor_sync(0xffffffffu, t1, 1));
        t1 = fmaxf(t1, __shfl_xor_sync(0xffffffffu, t1, 2));
        float mn0 = fmaxf(m0r, t0), mn1 = fmaxf(m1r, t1);
        float al0 = ex2f((m0r - mn0) * CEXP);
        float al1 = ex2f((m1r - mn1) * CEXP);
        m0r = mn0; m1r = mn1;
        const float mc0 = mn0 * CEXP, mc1 = mn1 * CEXP;
        float rs0 = 0.f, rs1 = 0.f;
        uint32_t pp[8][2];
#pragma unroll
        for (int j = 0; j < 8; j++) {
            float p0 = ex2f(fmaf(s[j][0], CEXP, -mc0));
            float p1 = ex2f(fmaf(s[j][1], CEXP, -mc0));
            float p2 = ex2f(fmaf(s[j][2], CEXP, -mc1));
            float p3 = ex2f(fmaf(s[j][3], CEXP, -mc1));
            rs0 += p0 + p1; rs1 += p2 + p3;
            pp[j][0] = pack_bf16x2(p0, p1);
            pp[j][1] = pack_bf16x2(p2, p3);
        }
        rs0 += __shfl_xor_sync(0xffffffffu, rs0, 1);
        rs0 += __shfl_xor_sync(0xffffffffu, rs0, 2);
        rs1 += __shfl_xor_sync(0xffffffffu, rs1, 1);
        rs1 += __shfl_xor_sync(0xffffffffu, rs1, 2);
        lr0 = lr0 * al0 + rs0;
        lr1 = lr1 * al1 + rs1;
#pragma unroll
        for (int j = 0; j < 8; j++) {
            o[j][0] *= al0; o[j][1] *= al0;
            o[j][2] *= al1; o[j][3] *= al1;
        }

        // ---- O += P V ----
#pragma unroll
        for (int t = 0; t < 4; t++) {
            uint32_t a[4] = { pp[2*t][0], pp[2*t][1], pp[2*t+1][0], pp[2*t+1][1] };
#pragma unroll
            for (int dp = 0; dp < 4; dp++) {
                uint32_t b0, b1, b2, b3;
                ldsm_x4_t(b0, b1, b2, b3,
                          sb + AV_OFF + buf * ATILEB
                          + (uint32_t)((t * 16 + (lane & 7) + ((lane >> 3) & 1) * 8) * ASTRB)
                          + (uint32_t)(dp * 32 + ((lane >> 4) & 1) * 16));
                mma16816(o[dp * 2],     a, b0, b1);
                mma16816(o[dp * 2 + 1], a, b2, b3);
            }
        }
        __syncthreads();
    }

    // ---- normalize + hi/lo split write ----
    const float inv0 = 1.f / lr0, inv1 = 1.f / lr1;
    const int r0 = b * SQL + q0 + wm + (lane >> 2);
    const int ecol = h * HD + (lane & 3) * 2;
#pragma unroll
    for (int j = 0; j < 8; j++) {
        float v0 = o[j][0] * inv0, v1 = o[j][1] * inv0;
        float v2 = o[j][2] * inv1, v3 = o[j][3] * inv1;
        __nv_bfloat16 h0 = __float2bfloat16(v0), h1 = __float2bfloat16(v1);
        __nv_bfloat16 h2 = __float2bfloat16(v2), h3 = __float2bfloat16(v3);
        size_t off0 = (size_t)r0 * EDIM + ecol + j * 8;
        size_t off1 = (size_t)(r0 + 8) * EDIM + ecol + j * 8;
        *(__nv_bfloat162*)(AOh + off0) = __nv_bfloat162(h0, h1);
        *(__nv_bfloat162*)(AOh + off1) = __nv_bfloat162(h2, h3);
        *(__nv_bfloat162*)(AOl + off0) = __nv_bfloat162(
            __float2bfloat16(v0 - __bfloat162float(h0)),
            __float2bfloat16(v1 - __bfloat162float(h1)));
        *(__nv_bfloat162*)(AOl + off1) = __nv_bfloat162(
            __float2bfloat16(v2 - __bfloat162float(h2)),
            __float2bfloat16(v3 - __bfloat162float(h3)));
    }
}

// ---------------- LayerNorm -------------------------------------------------
__global__ __launch_bounds__(256) void lnorm(
    const float* __restrict__ X, const float* __restrict__ ga,
    const float* __restrict__ be, float* __restrict__ out)
{
    __shared__ float rs[8], rs2[8];
    const int row = blockIdx.x, tid = threadIdx.x;
    const float* x = X + (size_t)row * EDIM;
    float4 v = *(const float4*)(x + tid * 4);
    float s = v.x + v.y + v.z + v.w;
    float s2 = v.x * v.x + v.y * v.y + v.z * v.z + v.w * v.w;
#pragma unroll
    for (int off = 16; off; off >>= 1) {
        s += __shfl_xor_sync(0xffffffffu, s, off);
        s2 += __shfl_xor_sync(0xffffffffu, s2, off);
    }
    if ((tid & 31) == 0) { rs[tid >> 5] = s; rs2[tid >> 5] = s2; }
    __syncthreads();
    if (tid < 32) {
        s = (tid < 8) ? rs[tid] : 0.f;
        s2 = (tid < 8) ? rs2[tid] : 0.f;
#pragma unroll
        for (int off = 4; off; off >>= 1) {
            s += __shfl_xor_sync(0xffffffffu, s, off);
            s2 += __shfl_xor_sync(0xffffffffu, s2, off);
        }
        if (tid == 0) { rs[0] = s; rs2[0] = s2; }
    }
    __syncthreads();
    float mu = rs[0] * (1.f / EDIM);
    float var = rs2[0] * (1.f / EDIM) - mu * mu;
    float r = rsqrtf(var + 1e-5f);
    float4 g4 = *(const float4*)(ga + tid * 4);
    float4 b4 = *(const float4*)(be + tid * 4);
    float4 o4;
    o4.x = (v.x - mu) * r * g4.x + b4.x;
    o4.y = (v.y - mu) * r * g4.y + b4.y;
    o4.z = (v.z - mu) * r * g4.z + b4.z;
    o4.w = (v.w - mu) * r * g4.w + b4.w;
    *(float4*)(out + (size_t)row * EDIM + tid * 4) = o4;
}

// ---------------------------------------------------------------------------
extern "C" void kernel_launch(void* const* d_in, const int* in_sizes, int n_in,
                              void* d_out, int out_size)
{
    const float* query = (const float*)d_in[0];
    const float* kv    = (const float*)d_in[1];
    const int*   mask  = (const int*)d_in[2];
    const float* Wq = (const float*)d_in[3];
    const float* bq = (const float*)d_in[4];
    const float* Wk = (const float*)d_in[5];
    const float* bk = (const float*)d_in[6];
    const float* Wv = (const float*)d_in[7];
    const float* bv = (const float*)d_in[8];
    const float* Wo = (const float*)d_in[9];
    const float* bo = (const float*)d_in[10];
    const float* lng = (const float*)d_in[11];
    const float* lnb = (const float*)d_in[12];
    float* out = (float*)d_out;

    __nv_bfloat16 *Qp, *Kp, *Vp;
    float* Xp;
    cudaGetSymbolAddress((void**)&Qp, g_Qb);
    cudaGetSymbolAddress((void**)&Kp, g_Kb);
    cudaGetSymbolAddress((void**)&Vp, g_Vb);
    cudaGetSymbolAddress((void**)&Xp, g_X);

    __nv_bfloat16 *qh, *ql, *kvh, *kvl, *aoh, *aol;
    __nv_bfloat16 *wqh, *wql, *wkh, *wkl, *wvh, *wvl, *woh, *wol;
    cudaGetSymbolAddress((void**)&qh, g_qh);   cudaGetSymbolAddress((void**)&ql, g_ql);
    cudaGetSymbolAddress((void**)&kvh, g_kvh); cudaGetSymbolAddress((void**)&kvl, g_kvl);
    cudaGetSymbolAddress((void**)&aoh, g_aoh); cudaGetSymbolAddress((void**)&aol, g_aol);
    cudaGetSymbolAddress((void**)&wqh, g_wqh); cudaGetSymbolAddress((void**)&wql, g_wql);
    cudaGetSymbolAddress((void**)&wkh, g_wkh); cudaGetSymbolAddress((void**)&wkl, g_wkl);
    cudaGetSymbolAddress((void**)&wvh, g_wvh); cudaGetSymbolAddress((void**)&wvl, g_wvl);
    cudaGetSymbolAddress((void**)&woh, g_woh); cudaGetSymbolAddress((void**)&wol, g_wol);

    static int attr_set = 0;
    if (!attr_set) {
        cudaFuncSetAttribute(gemm_mma,
                             cudaFuncAttributeMaxDynamicSharedMemorySize, GEMM_SMEM);
        cudaFuncSetAttribute(attn_mma,
                             cudaFuncAttributeMaxDynamicSharedMemorySize, ATT_SMEM);
        attr_set = 1;
    }

    const int W4 = EDIM * EDIM / 4;
    cvt_split<<<(MQ * EDIM / 4 + 255) / 256, 256>>>(query, qh, ql, MQ * EDIM / 4);
    cvt_split<<<(MKV * EDIM / 4 + 255) / 256, 256>>>(kv, kvh, kvl, MKV * EDIM / 4);
    cvt_split<<<(W4 + 255) / 256, 256>>>(Wq, wqh, wql, W4);
    cvt_split<<<(W4 + 255) / 256, 256>>>(Wk, wkh, wkl, W4);
    cvt_split<<<(W4 + 255) / 256, 256>>>(Wv, wvh, wvl, W4);
    cvt_split<<<(W4 + 255) / 256, 256>>>(Wo, woh, wol, W4);

    // projections -> bf16 [b][h][s][d]
    gemm_mma<<<dim3(EDIM / BN, MQ / BM), 256, GEMM_SMEM>>>(
        qh, ql, wqh, wql, bq, nullptr, Qp, SQL, 0);
    gemm_mma<<<dim3(EDIM / BN, MKV / BM), 256, GEMM_SMEM>>>(
        kvh, kvl, wkh, wkl, bk, nullptr, Kp, SKVL, 0);
    gemm_mma<<<dim3(EDIM / BN, MKV / BM), 256, GEMM_SMEM>>>(
        kvh, kvl, wvh, wvl, bv, nullptr, Vp, SKVL, 0);

    // tensor-core attention -> hi/lo bf16 AO
    attn_mma<<<dim3(SQL / 128, NH, NB), 256, ATT_SMEM>>>(Qp, Kp, Vp, mask, aoh, aol);

    // O projection + residual (fp32 out)
    gemm_mma<<<dim3(EDIM / BN, MQ / BM), 256, GEMM_SMEM>>>(
        aoh, aol, woh, wol, bo, query, Xp, SQL, 1);

    lnorm<<<MQ, 256>>>(Xp, lng, lnb, out);
}

// round 12
// speedup vs baseline: 3.6593x; 1.2174x over previous
#include <cuda_runtime.h>
#include <cuda_bf16.h>
#include <cstdint>

#define EDIM 1024
#define NH 16
#define HD 64
#define NB 2
#define SQL 1024
#define SKVL 4096
#define MQ (NB*SQL)
#define MKV (NB*SKVL)

// ---------------- scratch (__device__ globals; no allocs allowed) ----------
__device__ __align__(256) __nv_bfloat16 g_Qb[(size_t)NB*NH*SQL*HD];   // [b][h][sq][d]
__device__ __align__(256) __nv_bfloat16 g_Kb[(size_t)NB*NH*SKVL*HD];
__device__ __align__(256) __nv_bfloat16 g_Vb[(size_t)NB*NH*SKVL*HD];
__device__ __align__(256) float g_X[(size_t)MQ*EDIM];

__device__ __align__(256) __nv_bfloat16 g_qb[(size_t)MQ*EDIM];
__device__ __align__(256) __nv_bfloat16 g_kvb[(size_t)MKV*EDIM];
__device__ __align__(256) __nv_bfloat16 g_aob[(size_t)MQ*EDIM];
__device__ __align__(256) __nv_bfloat16 g_wqb[EDIM*EDIM];
__device__ __align__(256) __nv_bfloat16 g_wkb[EDIM*EDIM];
__device__ __align__(256) __nv_bfloat16 g_wvb[EDIM*EDIM];
__device__ __align__(256) __nv_bfloat16 g_wob[EDIM*EDIM];

// ---------------- baseline-ISA helpers ------------------------------------
__device__ __forceinline__ uint32_t smem_to_u32(const void* p) {
    uint32_t a;
    asm("{ .reg .u64 t; cvta.to.shared.u64 t, %1; cvt.u32.u64 %0, t; }"
        : "=r"(a) : "l"(p));
    return a;
}
#define CP_ASYNC16(dst, src) \
    asm volatile("cp.async.cg.shared.global [%0], [%1], 16;" :: "r"(dst), "l"(src) : "memory")
#define CP_COMMIT() asm volatile("cp.async.commit_group;" ::: "memory")
#define CP_WAIT1()  asm volatile("cp.async.wait_group 1;" ::: "memory")
#define CP_WAIT0()  asm volatile("cp.async.wait_group 0;" ::: "memory")

__device__ __forceinline__ void ldsm_x4(uint32_t& r0, uint32_t& r1,
                                        uint32_t& r2, uint32_t& r3, uint32_t addr) {
    asm volatile("ldmatrix.sync.aligned.m8n8.x4.shared.b16 {%0,%1,%2,%3}, [%4];"
                 : "=r"(r0), "=r"(r1), "=r"(r2), "=r"(r3) : "r"(addr));
}
__device__ __forceinline__ void ldsm_x4_t(uint32_t& r0, uint32_t& r1,
                                          uint32_t& r2, uint32_t& r3, uint32_t addr) {
    asm volatile("ldmatrix.sync.aligned.m8n8.x4.trans.shared.b16 {%0,%1,%2,%3}, [%4];"
                 : "=r"(r0), "=r"(r1), "=r"(r2), "=r"(r3) : "r"(addr));
}
__device__ __forceinline__ void mma16816(float* c, const uint32_t* a,
                                         uint32_t b0, uint32_t b1) {
    asm volatile(
        "mma.sync.aligned.m16n8k16.row.col.f32.bf16.bf16.f32 "
        "{%0,%1,%2,%3}, {%4,%5,%6,%7}, {%8,%9}, {%0,%1,%2,%3};"
        : "+f"(c[0]), "+f"(c[1]), "+f"(c[2]), "+f"(c[3])
        : "r"(a[0]), "r"(a[1]), "r"(a[2]), "r"(a[3]), "r"(b0), "r"(b1));
}
__device__ __forceinline__ float ex2f(float x) {
    float y; asm("ex2.approx.f32 %0, %1;" : "=f"(y) : "f"(x)); return y;
}
__device__ __forceinline__ uint32_t pack_bf16x2(float lo, float hi) {
    uint32_t r; asm("cvt.rn.bf16x2.f32 %0, %1, %2;" : "=r"(r) : "f"(hi), "f"(lo));
    return r;
}

// ---------------- fp32 -> bf16 convert -------------------------------------
__global__ __launch_bounds__(256) void cvt_bf16(
    const float* __restrict__ x, __nv_bfloat16* __restrict__ h, int n4)
{
    int i = blockIdx.x * 256 + threadIdx.x;
    if (i >= n4) return;
    float4 v = ((const float4*)x)[i];
    uint32_t p0 = pack_bf16x2(v.x, v.y);
    uint32_t p1 = pack_bf16x2(v.z, v.w);
    *(uint2*)(h + (size_t)i * 4) = make_uint2(p0, p1);
}

// ---------------- mma.sync GEMM (plain bf16): C = A @ W^T ------------------
// Tile 128x128x64, 8 warps (warp tile 64x32), cp.async double buffer,
// padded smem stride 144B. mode 0: +bias -> bf16 scatter [b][h][s][d].
// mode 1: +bias +residual -> fp32 [m][n].
#define BM 128
#define BN 128
#define BK 64
#define SROW 144
#define BOFF 18432
#define STAGE_BYTES 36864
#define GEMM_SMEM (2*STAGE_BYTES)
#define KSTAGES (EDIM/BK)          // 16

__device__ __forceinline__ void load_stage(
    uint32_t sb, int buf, int k0,
    const __nv_bfloat16* A, const __nv_bfloat16* B,
    int m0, int n0, int tid)
{
    uint32_t base = sb + buf * STAGE_BYTES;
#pragma unroll
    for (int r = 0; r < 4; r++) {
        int ch = tid + r * 256;              // 1024 chunks: 128 rows x 8 x 16B
        int row = ch >> 3, c = ch & 7;
        uint32_t off = (uint32_t)(row * SROW + c * 16);
        CP_ASYNC16(base + off,
                   (const char*)(A + (size_t)(m0 + row) * EDIM + k0) + c * 16);
        CP_ASYNC16(base + BOFF + off,
                   (const char*)(B + (size_t)(n0 + row) * EDIM + k0) + c * 16);
    }
}

__global__ __launch_bounds__(256, 1) void gemm_mma(
    const __nv_bfloat16* __restrict__ A, const __nv_bfloat16* __restrict__ B,
    const float* __restrict__ bias, const float* __restrict__ resid,
    void* __restrict__ Cout, int Sper, int mode)
{
    extern __shared__ char smem[];
    uint32_t sb = smem_to_u32(smem);
    const int tid = threadIdx.x, lane = tid & 31, wid = tid >> 5;
    const int m0 = blockIdx.y * BM, n0 = blockIdx.x * BN;
    const int wm = (wid & 1) * 64;
    const int wn = (wid >> 1) * 32;

    float acc[4][4][4];
#pragma unroll
    for (int i = 0; i < 4; i++)
#pragma unroll
        for (int j = 0; j < 4; j++)
#pragma unroll
            for (int t = 0; t < 4; t++) acc[i][j][t] = 0.f;

    load_stage(sb, 0, 0, A, B, m0, n0, tid);
    CP_COMMIT();

    const int rl = lane & 15;
    for (int kt = 0; kt < KSTAGES; kt++) {
        if (kt + 1 < KSTAGES) {
            load_stage(sb, (kt + 1) & 1, (kt + 1) * BK, A, B, m0, n0, tid);
            CP_COMMIT();
            CP_WAIT1();
        } else {
            CP_WAIT0();
        }
        __syncthreads();
        uint32_t base = sb + (kt & 1) * STAGE_BYTES;
#pragma unroll
        for (int kk = 0; kk < 4; kk++) {
            uint32_t rcol = (uint32_t)(kk * 32 + ((lane >> 4) << 4));
            uint32_t ah[4][4];
#pragma unroll
            for (int im = 0; im < 4; im++) {
                uint32_t ad = base + (uint32_t)((wm + im * 16 + rl) * SROW) + rcol;
                ldsm_x4(ah[im][0], ah[im][1], ah[im][2], ah[im][3], ad);
            }
            uint32_t bh[4][2];
#pragma unroll
            for (int pr = 0; pr < 2; pr++) {
                uint32_t bd = base + BOFF
                    + (uint32_t)((wn + pr * 16 + rl) * SROW) + rcol;
                uint32_t t0, t1, t2, t3;
                ldsm_x4(t0, t1, t2, t3, bd);
                bh[pr*2][0] = t0; bh[pr*2+1][0] = t1;
                bh[pr*2][1] = t2; bh[pr*2+1][1] = t3;
            }
#pragma unroll
            for (int im = 0; im < 4; im++)
#pragma unroll
                for (int in = 0; in < 4; in++)
                    mma16816(acc[im][in], ah[im], bh[in][0], bh[in][1]);
        }
        __syncthreads();
    }

    const int mr = m0 + wm + (lane >> 2);
    const int nc = n0 + wn + (lane & 3) * 2;
#pragma unroll
    for (int im = 0; im < 4; im++) {
#pragma unroll
        for (int half = 0; half < 2; half++) {
            const int m = mr + im * 16 + half * 8;
            const int bi = m / Sper, si = m - bi * Sper;
#pragma unroll
            for (int in = 0; in < 4; in++) {
                const int n = nc + in * 8;
                float c0 = acc[im][in][half * 2 + 0] + bias[n];
                float c1 = acc[im][in][half * 2 + 1] + bias[n + 1];
                if (mode == 0) {
                    const int h = n >> 6, d = n & 63;
                    __nv_bfloat16* dst = (__nv_bfloat16*)Cout +
                        ((size_t)((bi * NH + h) * Sper + si)) * HD + d;
                    *(uint32_t*)dst = pack_bf16x2(c0, c1);
                } else {
                    const size_t off = (size_t)m * EDIM + n;
                    float2 q2 = *(const float2*)(resid + off);
                    *(float2*)((float*)Cout + off) = make_float2(c0 + q2.x, c1 + q2.y);
                }
            }
        }
    }
}

// ---------------- tensor-core flash attention ------------------------------
// CTA: 128 q-rows x (head, batch); 8 warps x 16 rows; KV tiles of 64,
// double-buffered cp.async. bf16 MMAs, fp32 softmax (ex2.approx), in-register
// P repack. Emits plain bf16 AO.
#define ASTRB 144
#define ATILEB (64*ASTRB)
#define AQ_OFF 0
#define AK_OFF (128*ASTRB)
#define AV_OFF (AK_OFF + 2*ATILEB)
#define AB_OFF (AV_OFF + 2*ATILEB)
#define ATT_SMEM (AB_OFF + 2*64*4)
#define NKV (SKVL/64)
#define CEXP 0.18033688f  /* log2(e)/8 */

__device__ __forceinline__ void load_kv_tile(
    uint32_t sb, int buf, int kv0,
    const __nv_bfloat16* Kb, const __nv_bfloat16* Vb, int tid)
{
#pragma unroll
    for (int i = 0; i < 2; i++) {
        int ch = tid + i * 256;
        int row = ch >> 3, c = ch & 7;
        uint32_t off = (uint32_t)(buf * ATILEB + row * ASTRB + c * 16);
        CP_ASYNC16(sb + AK_OFF + off, (const char*)(Kb + (size_t)(kv0 + row) * HD) + c * 16);
        CP_ASYNC16(sb + AV_OFF + off, (const char*)(Vb + (size_t)(kv0 + row) * HD) + c * 16);
    }
}

__global__ __launch_bounds__(256, 1) void attn_mma(
    const __nv_bfloat16* __restrict__ Qg, const __nv_bfloat16* __restrict__ Kg,
    const __nv_bfloat16* __restrict__ Vg, const int* __restrict__ maskg,
    __nv_bfloat16* __restrict__ AO)
{
    extern __shared__ char smem[];
    uint32_t sb = smem_to_u32(smem);
    float* biasS = (float*)(smem + AB_OFF);
    const int tid = threadIdx.x, lane = tid & 31, wid = tid >> 5;
    const int q0 = blockIdx.x * 128;
    const int h = blockIdx.y, b = blockIdx.z;
    const __nv_bfloat16* Qb = Qg + ((size_t)((b * NH + h) * SQL + q0)) * HD;
    const __nv_bfloat16* Kb = Kg + (size_t)(b * NH + h) * SKVL * HD;
    const __nv_bfloat16* Vb = Vg + (size_t)(b * NH + h) * SKVL * HD;
    const int* mb = maskg + b * SKVL;
    const int wm = wid * 16;

#pragma unroll
    for (int i = 0; i < 4; i++) {
        int ch = tid + i * 256;
        int row = ch >> 3, c = ch & 7;
        CP_ASYNC16(sb + AQ_OFF + row * ASTRB + c * 16,
                   (const char*)(Qb + row * HD) + c * 16);
    }
    load_kv_tile(sb, 0, 0, Kb, Vb, tid);
    CP_COMMIT();
    if (tid < 64) biasS[tid] = mb[tid] ? 0.f : -1e30f;

    float m0r = -1e30f, m1r = -1e30f, lr0 = 0.f, lr1 = 0.f;
    float o[8][4];
#pragma unroll
    for (int j = 0; j < 8; j++)
#pragma unroll
        for (int t = 0; t < 4; t++) o[j][t] = 0.f;

    for (int kt = 0; kt < NKV; kt++) {
        const int buf = kt & 1;
        if (kt + 1 < NKV) {
            load_kv_tile(sb, buf ^ 1, (kt + 1) * 64, Kb, Vb, tid);
            if (tid < 64)
                biasS[64 * (buf ^ 1) + tid] = mb[(kt + 1) * 64 + tid] ? 0.f : -1e30f;
            CP_COMMIT();
            CP_WAIT1();
        } else {
            CP_WAIT0();
        }
        __syncthreads();

        float s[8][4];
#pragma unroll
        for (int j = 0; j < 8; j++)
#pragma unroll
            for (int t = 0; t < 4; t++) s[j][t] = 0.f;
#pragma unroll
        for (int kk = 0; kk < 4; kk++) {
            uint32_t a[4];
            ldsm_x4(a[0], a[1], a[2], a[3],
                    sb + AQ_OFF + (uint32_t)((wm + (lane & 15)) * ASTRB)
                    + (uint32_t)(kk * 32 + (lane >> 4) * 16));
#pragma unroll
            for (int jp = 0; jp < 4; jp++) {
                uint32_t b0, b1, b2, b3;
                ldsm_x4(b0, b1, b2, b3,
                        sb + AK_OFF + buf * ATILEB
                        + (uint32_t)((jp * 16 + (lane & 7) + ((lane >> 4) & 1) * 8) * ASTRB)
                        + (uint32_t)(kk * 32 + ((lane >> 3) & 1) * 16));
                mma16816(s[jp * 2],     a, b0, b1);
                mma16816(s[jp * 2 + 1], a, b2, b3);
            }
        }

        const int qr = (lane & 3) * 2;
        float t0 = -1e30f, t1 = -1e30f;
#pragma unroll
        for (int j = 0; j < 8; j++) {
            float2 bv = *(float2*)&biasS[buf * 64 + j * 8 + qr];
            s[j][0] += bv.x; s[j][1] += bv.y;
            s[j][2] += bv.x; s[j][3] += bv.y;
            t0 = fmaxf(t0, fmaxf(s[j][0], s[j][1]));
            t1 = fmaxf(t1, fmaxf(s[j][2], s[j][3]));
        }
        t0 = fmaxf(t0, __shfl_xor_sync(0xffffffffu, t0, 1));
        t0 = fmaxf(t0, __shfl_xor_sync(0xffffffffu, t0, 2));
        t1 = fmaxf(t1, __shfl_xor_sync(0xffffffffu, t1, 1));
        t1 = fmaxf(t1, __shfl_xor_sync(0xffffffffu, t1, 2));
        float mn0 = fmaxf(m0r, t0), mn1 = fmaxf(m1r, t1);
        float al0 = ex2f((m0r - mn0) * CEXP);
        float al1 = ex2f((m1r - mn1) * CEXP);
        m0r = mn0; m1r = mn1;
        const float mc0 = mn0 * CEXP, mc1 = mn1 * CEXP;
        float rs0 = 0.f, rs1 = 0.f;
        uint32_t pp[8][2];
#pragma unroll
        for (int j = 0; j < 8; j++) {
            float p0 = ex2f(fmaf(s[j][0], CEXP, -mc0));
            float p1 = ex2f(fmaf(s[j][1], CEXP, -mc0));
            float p2 = ex2f(fmaf(s[j][2], CEXP, -mc1));
            float p3 = ex2f(fmaf(s[j][3], CEXP, -mc1));
            rs0 += p0 + p1; rs1 += p2 + p3;
            pp[j][0] = pack_bf16x2(p0, p1);
            pp[j][1] = pack_bf16x2(p2, p3);
        }
        rs0 += __shfl_xor_sync(0xffffffffu, rs0, 1);
        rs0 += __shfl_xor_sync(0xffffffffu, rs0, 2);
        rs1 += __shfl_xor_sync(0xffffffffu, rs1, 1);
        rs1 += __shfl_xor_sync(0xffffffffu, rs1, 2);
        lr0 = lr0 * al0 + rs0;
        lr1 = lr1 * al1 + rs1;
#pragma unroll
        for (int j = 0; j < 8; j++) {
            o[j][0] *= al0; o[j][1] *= al0;
            o[j][2] *= al1; o[j][3] *= al1;
        }

#pragma unroll
        for (int t = 0; t < 4; t++) {
            uint32_t a[4] = { pp[2*t][0], pp[2*t][1], pp[2*t+1][0], pp[2*t+1][1] };
#pragma unroll
            for (int dp = 0; dp < 4; dp++) {
                uint32_t b0, b1, b2, b3;
                ldsm_x4_t(b0, b1, b2, b3,
                          sb + AV_OFF + buf * ATILEB
                          + (uint32_t)((t * 16 + (lane & 7) + ((lane >> 3) & 1) * 8) * ASTRB)
                          + (uint32_t)(dp * 32 + ((lane >> 4) & 1) * 16));
                mma16816(o[dp * 2],     a, b0, b1);
                mma16816(o[dp * 2 + 1], a, b2, b3);
            }
        }
        __syncthreads();
    }

    const float inv0 = 1.f / lr0, inv1 = 1.f / lr1;
    const int r0 = b * SQL + q0 + wm + (lane >> 2);
    const int ecol = h * HD + (lane & 3) * 2;
#pragma unroll
    for (int j = 0; j < 8; j++) {
        size_t off0 = (size_t)r0 * EDIM + ecol + j * 8;
        size_t off1 = (size_t)(r0 + 8) * EDIM + ecol + j * 8;
        *(uint32_t*)(AO + off0) = pack_bf16x2(o[j][0] * inv0, o[j][1] * inv0);
        *(uint32_t*)(AO + off1) = pack_bf16x2(o[j][2] * inv1, o[j][3] * inv1);
    }
}

// ---------------- LayerNorm -------------------------------------------------
__global__ __launch_bounds__(256) void lnorm(
    const float* __restrict__ X, const float* __restrict__ ga,
    const float* __restrict__ be, float* __restrict__ out)
{
    __shared__ float rs[8], rs2[8];
    const int row = blockIdx.x, tid = threadIdx.x;
    const float* x = X + (size_t)row * EDIM;
    float4 v = *(const float4*)(x + tid * 4);
    float s = v.x + v.y + v.z + v.w;
    float s2 = v.x * v.x + v.y * v.y + v.z * v.z + v.w * v.w;
#pragma unroll
    for (int off = 16; off; off >>= 1) {
        s += __shfl_xor_sync(0xffffffffu, s, off);
        s2 += __shfl_xor_sync(0xffffffffu, s2, off);
    }
    if ((tid & 31) == 0) { rs[tid >> 5] = s; rs2[tid >> 5] = s2; }
    __syncthreads();
    if (tid < 32) {
        s = (tid < 8) ? rs[tid] : 0.f;
        s2 = (tid < 8) ? rs2[tid] : 0.f;
#pragma unroll
        for (int off = 4; off; off >>= 1) {
            s += __shfl_xor_sync(0xffffffffu, s, off);
            s2 += __shfl_xor_sync(0xffffffffu, s2, off);
        }
        if (tid == 0) { rs[0] = s; rs2[0] = s2; }
    }
    __syncthreads();
    float mu = rs[0] * (1.f / EDIM);
    float var = rs2[0] * (1.f / EDIM) - mu * mu;
    float r = rsqrtf(var + 1e-5f);
    float4 g4 = *(const float4*)(ga + tid * 4);
    float4 b4 = *(const float4*)(be + tid * 4);
    float4 o4;
    o4.x = (v.x - mu) * r * g4.x + b4.x;
    o4.y = (v.y - mu) * r * g4.y + b4.y;
    o4.z = (v.z - mu) * r * g4.z + b4.z;
    o4.w = (v.w - mu) * r * g4.w + b4.w;
    *(float4*)(out + (size_t)row * EDIM + tid * 4) = o4;
}

// ---------------------------------------------------------------------------
extern "C" void kernel_launch(void* const* d_in, const int* in_sizes, int n_in,
                              void* d_out, int out_size)
{
    const float* query = (const float*)d_in[0];
    const float* kv    = (const float*)d_in[1];
    const int*   mask  = (const int*)d_in[2];
    const float* Wq = (const float*)d_in[3];
    const float* bq = (const float*)d_in[4];
    const float* Wk = (const float*)d_in[5];
    const float* bk = (const float*)d_in[6];
    const float* Wv = (const float*)d_in[7];
    const float* bv = (const float*)d_in[8];
    const float* Wo = (const float*)d_in[9];
    const float* bo = (const float*)d_in[10];
    const float* lng = (const float*)d_in[11];
    const float* lnb = (const float*)d_in[12];
    float* out = (float*)d_out;

    __nv_bfloat16 *Qp, *Kp, *Vp;
    float* Xp;
    cudaGetSymbolAddress((void**)&Qp, g_Qb);
    cudaGetSymbolAddress((void**)&Kp, g_Kb);
    cudaGetSymbolAddress((void**)&Vp, g_Vb);
    cudaGetSymbolAddress((void**)&Xp, g_X);

    __nv_bfloat16 *qb, *kvb, *aob, *wqb, *wkb, *wvb, *wob;
    cudaGetSymbolAddress((void**)&qb, g_qb);
    cudaGetSymbolAddress((void**)&kvb, g_kvb);
    cudaGetSymbolAddress((void**)&aob, g_aob);
    cudaGetSymbolAddress((void**)&wqb, g_wqb);
    cudaGetSymbolAddress((void**)&wkb, g_wkb);
    cudaGetSymbolAddress((void**)&wvb, g_wvb);
    cudaGetSymbolAddress((void**)&wob, g_wob);

    static int attr_set = 0;
    if (!attr_set) {
        cudaFuncSetAttribute(gemm_mma,
                             cudaFuncAttributeMaxDynamicSharedMemorySize, GEMM_SMEM);
        cudaFuncSetAttribute(attn_mma,
                             cudaFuncAttributeMaxDynamicSharedMemorySize, ATT_SMEM);
        attr_set = 1;
    }

    const int W4 = EDIM * EDIM / 4;
    cvt_bf16<<<(MQ * EDIM / 4 + 255) / 256, 256>>>(query, qb, MQ * EDIM / 4);
    cvt_bf16<<<(MKV * EDIM / 4 + 255) / 256, 256>>>(kv, kvb, MKV * EDIM / 4);
    cvt_bf16<<<(W4 + 255) / 256, 256>>>(Wq, wqb, W4);
    cvt_bf16<<<(W4 + 255) / 256, 256>>>(Wk, wkb, W4);
    cvt_bf16<<<(W4 + 255) / 256, 256>>>(Wv, wvb, W4);
    cvt_bf16<<<(W4 + 255) / 256, 256>>>(Wo, wob, W4);

    // projections -> bf16 [b][h][s][d]
    gemm_mma<<<dim3(EDIM / BN, MQ / BM), 256, GEMM_SMEM>>>(
        qb, wqb, bq, nullptr, Qp, SQL, 0);
    gemm_mma<<<dim3(EDIM / BN, MKV / BM), 256, GEMM_SMEM>>>(
        kvb, wkb, bk, nullptr, Kp, SKVL, 0);
    gemm_mma<<<dim3(EDIM / BN, MKV / BM), 256, GEMM_SMEM>>>(
        kvb, wvb, bv, nullptr, Vp, SKVL, 0);

    // tensor-core attention -> bf16 AO
    attn_mma<<<dim3(SQL / 128, NH, NB), 256, ATT_SMEM>>>(Qp, Kp, Vp, mask, aob);

    // O projection + residual (fp32 out)
    gemm_mma<<<dim3(EDIM / BN, MQ / BM), 256, GEMM_SMEM>>>(
        aob, wob, bo, query, Xp, SQL, 1);

    lnorm<<<MQ, 256>>>(Xp, lng, lnb, out);
}